// round 10
// baseline (speedup 1.0000x reference)
#include <cuda_runtime.h>
#include <cuda_fp16.h>
#include <math.h>
#include <stdint.h>

#define EMB 2048
#define NB 1024
#define NH 32
#define HS 64
#define SROWS 66

// ================= device scratch =================
__device__ float g_xn [NB * EMB];
__device__ float g_sx [NB * EMB];
__device__ float g_xin[NB * EMB];
__device__ float g_x5 [NB * 320];
__device__ float g_r  [NB * EMB];
__device__ float g_k  [NB * EMB];
__device__ float g_v  [NB * EMB];
__device__ float g_g  [NB * EMB];
__device__ float g_x1 [NB * EMB];
__device__ float g_rr [NB * EMB];

__device__ __half h_xr [NB * EMB];
__device__ __half h_xk [NB * EMB];
__device__ __half h_xv [NB * EMB];
__device__ __half h_xg [NB * EMB];
__device__ __half h_ygg[NB * EMB];
__device__ __half h_xk2[NB * EMB];
__device__ __half h_xr2[NB * EMB];
__device__ __half h_kk [NB * EMB];
__device__ __half h_w  [8 * EMB * EMB];   // converted weights

// ================= helpers =================
__device__ __forceinline__ uint32_t smem_u32(const void* p) {
    uint32_t a;
    asm("{ .reg .u64 t; cvta.to.shared.u64 t, %1; cvt.u32.u64 %0, t; }" : "=r"(a) : "l"(p));
    return a;
}

#define CP_ASYNC16(dst, src) \
    asm volatile("cp.async.cg.shared.global [%0], [%1], 16;" :: "r"(dst), "l"(src))
#define CP_COMMIT() asm volatile("cp.async.commit_group;" ::: "memory")
#define CP_WAIT0()  asm volatile("cp.async.wait_group 0;" ::: "memory")
#define CP_WAIT1()  asm volatile("cp.async.wait_group 1;" ::: "memory")

__device__ __forceinline__ void mma_f16(float& c0, float& c1, float& c2, float& c3,
                                        uint32_t a0, uint32_t a1, uint32_t a2, uint32_t a3,
                                        uint32_t b0, uint32_t b1) {
    asm volatile(
        "mma.sync.aligned.m16n8k16.row.col.f32.f16.f16.f32 "
        "{%0,%1,%2,%3}, {%4,%5,%6,%7}, {%8,%9}, {%0,%1,%2,%3};"
        : "+f"(c0), "+f"(c1), "+f"(c2), "+f"(c3)
        : "r"(a0), "r"(a1), "r"(a2), "r"(a3), "r"(b0), "r"(b1));
}

// ================= fused LayerNorm1 + weight fp32->fp16 conversion =================
struct WCvt { const float* src[8]; };
#define WCVT_BLKS_PER_W 4096   // (2048*2048)/(256*4)

__global__ __launch_bounds__(256) void ln1_wcvt_kernel(
    const float* __restrict__ x, const float* __restrict__ state,
    const float* __restrict__ w, const float* __restrict__ bvec,
    const float* __restrict__ maa_x, const int* __restrict__ ip,
    const WCvt wc)
{
    int bid = blockIdx.x;
    int t = threadIdx.x;
    if (bid >= NB) {
        // weight conversion part
        int r = bid - NB;
        int z = r >> 12;            // / 4096
        int blk = r & 4095;
        const float* s = wc.src[z];
        __half* d = h_w + (size_t)z * EMB * EMB;
        int i = (blk * 256 + t) * 4;
        float4 f = *(const float4*)(s + i);
        __half2 lo = __floats2half2_rn(f.x, f.y);
        __half2 hi = __floats2half2_rn(f.z, f.w);
        *(uint2*)(d + i) = make_uint2(*(uint32_t*)&lo, *(uint32_t*)&hi);
        return;
    }
    // LayerNorm 1 part
    __shared__ float sh[8], sh2[8];
    int b = bid;
    const float* xr = x + (size_t)b * EMB;
    float v[8];
    float s = 0.f, s2 = 0.f;
#pragma unroll
    for (int u = 0; u < 2; u++) {
        float4 f = *(const float4*)(xr + t * 8 + u * 4);
        v[u*4+0] = f.x; v[u*4+1] = f.y; v[u*4+2] = f.z; v[u*4+3] = f.w;
    }
#pragma unroll
    for (int q = 0; q < 8; q++) { s += v[q]; s2 += v[q] * v[q]; }
#pragma unroll
    for (int o = 16; o > 0; o >>= 1) {
        s  += __shfl_xor_sync(0xffffffffu, s,  o);
        s2 += __shfl_xor_sync(0xffffffffu, s2, o);
    }
    if ((t & 31) == 0) { sh[t >> 5] = s; sh2[t >> 5] = s2; }
    __syncthreads();
    s = 0.f; s2 = 0.f;
#pragma unroll
    for (int q = 0; q < 8; q++) { s += sh[q]; s2 += sh2[q]; }
    float mu  = s * (1.0f / EMB);
    float var = s2 * (1.0f / EMB) - mu * mu;
    float rinv = rsqrtf(var + 1e-5f);
    int i = ip[0];
    const float* srow = state + ((size_t)b * SROWS + (size_t)((2 + HS) * i + 1)) * EMB;
#pragma unroll
    for (int q = 0; q < 8; q++) {
        int e = t * 8 + q;
        float xnv = (v[q] - mu) * rinv * w[e] + bvec[e];
        float sxv = srow[e] - xnv;
        size_t o = (size_t)b * EMB + e;
        g_xn[o] = xnv;
        g_sx[o] = sxv;
        g_xin[o] = xnv + sxv * maa_x[e];
    }
}

// ================= fp16 mma GEMM NT (batched over blockIdx.z) =================
// 256 threads, 8 warps 2(M)x4(N); warp tile 64x32; CTA 128x128; TK=64; 2 stages.
#define TM 128
#define TN 128
#define TK 64
#define PADH 72                       // halfs per smem row (64 + 8 pad)
#define ATILE_H (TM * PADH)           // 9216 halfs
#define STG_H (2 * ATILE_H)
#define STG_BYTES (STG_H * 2)         // 36864 B
#define NC (EMB / TK)                 // 32
#define GSMEM_BYTES (2 * STG_BYTES)   // 73728

// EP: 0 none, 1 silu, 2 sigmoid, 3 relu^2 -> half, 4 add, 5 add + gate*acc
struct GemmB {
    const __half* A[4];
    const __half* W[4];
    float* C[4];
    __half* Ch[4];
    const float* addp[4];
    const float* gatep[4];
    int ep[4];
};

__global__ void __launch_bounds__(256, 2) gemm_mma(const GemmB q)
{
    extern __shared__ __align__(16) __half smem[];
    int z = blockIdx.z;
    const __half* Ag = q.A[z];
    const __half* Wg = q.W[z];
    float* C = q.C[z];
    __half* Ch = q.Ch[z];
    const float* add  = q.addp[z];
    const float* gate = q.gatep[z];
    int ep = q.ep[z];

    int tid  = threadIdx.x;
    int lane = tid & 31;
    int wid  = tid >> 5;
    int wm = wid >> 2, wn = wid & 3;
    int gq = lane >> 2, tq = lane & 3;

    int m0 = blockIdx.y * TM;
    int n0 = blockIdx.x * TN;

    const __half* Abase = Ag + (size_t)m0 * EMB;
    const __half* Wbase = Wg + (size_t)n0 * EMB;

    uint32_t smem_b = smem_u32(smem);

    int srow = tid >> 1;              // 0..127
    int scol = (tid & 1) * 8;         // +16*i, i=0..3

    float acc[4][4][4];
#pragma unroll
    for (int i = 0; i < 4; i++)
#pragma unroll
        for (int j = 0; j < 4; j++)
#pragma unroll
            for (int u = 0; u < 4; u++) acc[i][j][u] = 0.f;

    // prologue: chunk 0 -> stage 0
    {
        uint32_t sA = smem_b;
        uint32_t sB = sA + ATILE_H * 2;
#pragma unroll
        for (int i = 0; i < 4; i++) {
            int col = scol + i * 16;
            CP_ASYNC16(sA + (srow * PADH + col) * 2, Abase + (size_t)srow * EMB + col);
            CP_ASYNC16(sB + (srow * PADH + col) * 2, Wbase + (size_t)srow * EMB + col);
        }
        CP_COMMIT();
    }

    for (int c = 0; c < NC; c++) {
        int s = c & 1;
        if (c + 1 < NC) {
            uint32_t sA = smem_b + (s ^ 1) * STG_BYTES;
            uint32_t sB = sA + ATILE_H * 2;
            int k0 = (c + 1) * TK;
#pragma unroll
            for (int i = 0; i < 4; i++) {
                int col = scol + i * 16;
                CP_ASYNC16(sA + (srow * PADH + col) * 2, Abase + (size_t)srow * EMB + k0 + col);
                CP_ASYNC16(sB + (srow * PADH + col) * 2, Wbase + (size_t)srow * EMB + k0 + col);
            }
            CP_COMMIT();
            CP_WAIT1();
        } else {
            CP_WAIT0();
        }
        __syncthreads();

        const uint32_t* As32 = reinterpret_cast<const uint32_t*>(smem + s * STG_H);
        const uint32_t* Bs32 = As32 + ATILE_H / 2;

#pragma unroll
        for (int ks = 0; ks < 4; ks++) {
            int kb2 = ks * 8;         // u32 offset of this k16 block
            uint32_t a[4][4];
#pragma unroll
            for (int ma = 0; ma < 4; ma++) {
                int row = wm * 64 + ma * 16 + gq;
                int base = row * (PADH / 2) + kb2 + tq;
                a[ma][0] = As32[base];
                a[ma][1] = As32[base + 8 * (PADH / 2)];
                a[ma][2] = As32[base + 4];
                a[ma][3] = As32[base + 8 * (PADH / 2) + 4];
            }
            uint32_t b[4][2];
#pragma unroll
            for (int na = 0; na < 4; na++) {
                int col = wn * 32 + na * 8 + gq;
                int base = col * (PADH / 2) + kb2 + tq;
                b[na][0] = Bs32[base];
                b[na][1] = Bs32[base + 4];
            }
#pragma unroll
            for (int ma = 0; ma < 4; ma++)
#pragma unroll
                for (int na = 0; na < 4; na++)
                    mma_f16(acc[ma][na][0], acc[ma][na][1], acc[ma][na][2], acc[ma][na][3],
                            a[ma][0], a[ma][1], a[ma][2], a[ma][3],
                            b[na][0], b[na][1]);
        }
        __syncthreads();
    }

#pragma unroll
    for (int ma = 0; ma < 4; ma++) {
#pragma unroll
        for (int na = 0; na < 4; na++) {
            int r0 = m0 + wm * 64 + ma * 16 + gq;
            int c0 = n0 + wn * 32 + na * 8 + 2 * tq;
#pragma unroll
            for (int half_ = 0; half_ < 2; half_++) {
                int rr = r0 + half_ * 8;
                size_t o = (size_t)rr * EMB + c0;
                float v0 = acc[ma][na][half_ * 2 + 0];
                float v1 = acc[ma][na][half_ * 2 + 1];
                if (ep == 1)      { v0 = v0 / (1.f + expf(-v0)); v1 = v1 / (1.f + expf(-v1)); }
                else if (ep == 2) { v0 = 1.f / (1.f + expf(-v0)); v1 = 1.f / (1.f + expf(-v1)); }
                else if (ep == 3) {
                    v0 = fmaxf(v0, 0.f); v1 = fmaxf(v1, 0.f);
                    __half2 hv = __floats2half2_rn(v0 * v0, v1 * v1);
                    *(uint32_t*)(Ch + o) = *(uint32_t*)&hv;
                    continue;
                }
                else if (ep == 4) { v0 = add[o] + v0; v1 = add[o + 1] + v1; }
                else if (ep == 5) { v0 = add[o] + gate[o] * v0; v1 = add[o + 1] + gate[o + 1] * v1; }
                *(float2*)(C + o) = make_float2(v0, v1);
            }
        }
    }
}

// ================= LayerNorm 2 (outputs half) =================
__global__ __launch_bounds__(256) void ln2_kernel(
    const float* __restrict__ state,
    const float* __restrict__ w, const float* __restrict__ bvec,
    const float* __restrict__ fmk, const float* __restrict__ fmr,
    const int* __restrict__ ip)
{
    __shared__ float sh[8], sh2[8];
    int b = blockIdx.x, t = threadIdx.x;
    const float* xr = g_x1 + (size_t)b * EMB;
    float v[8];
    float s = 0.f, s2 = 0.f;
#pragma unroll
    for (int u = 0; u < 2; u++) {
        float4 f = *(const float4*)(xr + t * 8 + u * 4);
        v[u*4+0] = f.x; v[u*4+1] = f.y; v[u*4+2] = f.z; v[u*4+3] = f.w;
    }
#pragma unroll
    for (int q = 0; q < 8; q++) { s += v[q]; s2 += v[q] * v[q]; }
#pragma unroll
    for (int o = 16; o > 0; o >>= 1) {
        s  += __shfl_xor_sync(0xffffffffu, s,  o);
        s2 += __shfl_xor_sync(0xffffffffu, s2, o);
    }
    if ((t & 31) == 0) { sh[t >> 5] = s; sh2[t >> 5] = s2; }
    __syncthreads();
    s = 0.f; s2 = 0.f;
#pragma unroll
    for (int q = 0; q < 8; q++) { s += sh[q]; s2 += sh2[q]; }
    float mu  = s * (1.0f / EMB);
    float var = s2 * (1.0f / EMB) - mu * mu;
    float rinv = rsqrtf(var + 1e-5f);
    int i = ip[0];
    const float* srow = state + ((size_t)b * SROWS + (size_t)((2 + HS) * i)) * EMB;
#pragma unroll
    for (int q = 0; q < 8; q++) {
        int e = t * 8 + q;
        float xnv = (v[q] - mu) * rinv * w[e] + bvec[e];
        float sxv = srow[e] - xnv;
        size_t o = (size_t)b * EMB + e;
        h_xk2[o] = __float2half(xnv + sxv * fmk[e]);
        h_xr2[o] = __float2half(xnv + sxv * fmr[e]);
    }
}

// ================= small GEMM: x5 = tanh(xin @ maa_w1), tile 32x64 ====
__global__ __launch_bounds__(256) void gemm_w1_tanh(const float* __restrict__ W1)
{
    __shared__ float As[16][36];
    __shared__ float Ws[16][68];
    int t = threadIdx.x;
    int bm0 = blockIdx.y * 32, bn0 = blockIdx.x * 64;
    int tm = (t >> 4) * 2, tn = (t & 15) * 4;
    float acc[2][4] = {};
    for (int k0 = 0; k0 < EMB; k0 += 16) {
        float2 a = *(const float2*)(g_xin + (size_t)(bm0 + (t >> 3)) * EMB + k0 + (t & 7) * 2);
        float4 w = *(const float4*)(W1 + (size_t)(k0 + (t >> 4)) * 320 + bn0 + (t & 15) * 4);
        __syncthreads();
        As[(t & 7) * 2 + 0][t >> 3] = a.x;
        As[(t & 7) * 2 + 1][t >> 3] = a.y;
        *(float4*)&Ws[t >> 4][(t & 15) * 4] = w;
        __syncthreads();
#pragma unroll
        for (int kk = 0; kk < 16; kk++) {
            float ra[2], rw[4];
#pragma unroll
            for (int q = 0; q < 2; q++) ra[q] = As[kk][tm + q];
#pragma unroll
            for (int q = 0; q < 4; q++) rw[q] = Ws[kk][tn + q];
#pragma unroll
            for (int iq = 0; iq < 2; iq++)
#pragma unroll
                for (int jq = 0; jq < 4; jq++)
                    acc[iq][jq] += ra[iq] * rw[jq];
        }
    }
#pragma unroll
    for (int iq = 0; iq < 2; iq++)
#pragma unroll
        for (int jq = 0; jq < 4; jq++) {
            int m = bm0 + tm + iq, n = bn0 + tn + jq;
            g_x5[(size_t)m * 320 + n] = tanhf(acc[iq][jq]);
        }
}

// ================= mix (outputs half) =================
__global__ __launch_bounds__(256) void mix_kernel(
    const float* __restrict__ maa_w2,
    const float* __restrict__ mk, const float* __restrict__ mv,
    const float* __restrict__ mr, const float* __restrict__ mg)
{
    __shared__ float As[16][68];
    __shared__ float Ws[16][68];
    int z = blockIdx.z, jj = z + 1;
    const float* A = g_x5 + jj * 64;
    const float* W = maa_w2 + (size_t)jj * 64 * EMB;
    const float* vec = (z == 0) ? mk : (z == 1) ? mv : (z == 2) ? mr : mg;
    __half* out = (z == 0) ? h_xk : (z == 1) ? h_xv : (z == 2) ? h_xr : h_xg;
    int t = threadIdx.x;
    int bm0 = blockIdx.y * 64, bn0 = blockIdx.x * 64;
    int tm = (t >> 4) * 4, tn = (t & 15) * 4;
    float acc[4][4] = {};
    for (int k0 = 0; k0 < 64; k0 += 16) {
        float4 a = *(const float4*)(A + (size_t)(bm0 + (t >> 2)) * 320 + k0 + (t & 3) * 4);
        float4 w = *(const float4*)(W + (size_t)(k0 + (t >> 4)) * EMB + bn0 + (t & 15) * 4);
        __syncthreads();
        As[(t&3)*4+0][t>>2] = a.x; As[(t&3)*4+1][t>>2] = a.y;
        As[(t&3)*4+2][t>>2] = a.z; As[(t&3)*4+3][t>>2] = a.w;
        *(float4*)&Ws[t >> 4][(t & 15) * 4] = w;
        __syncthreads();
#pragma unroll
        for (int kk = 0; kk < 16; kk++) {
            float ra[4], rw[4];
#pragma unroll
            for (int q = 0; q < 4; q++) ra[q] = As[kk][tm + q];
#pragma unroll
            for (int q = 0; q < 4; q++) rw[q] = Ws[kk][tn + q];
#pragma unroll
            for (int iq = 0; iq < 4; iq++)
#pragma unroll
                for (int jq = 0; jq < 4; jq++)
                    acc[iq][jq] += ra[iq] * rw[jq];
        }
    }
#pragma unroll
    for (int iq = 0; iq < 4; iq++)
#pragma unroll
        for (int jq = 0; jq < 4; jq++) {
            int m = bm0 + tm + iq, n = bn0 + tn + jq;
            size_t o = (size_t)m * EMB + n;
            out[o] = __float2half(g_xn[o] + g_sx[o] * (vec[n] + acc[iq][jq]));
        }
}

// ================= WKV + GroupNorm + gate (output half) =================
__global__ __launch_bounds__(256) void wkv_kernel(
    const float* __restrict__ faaaa, const float* __restrict__ state,
    const float* __restrict__ gn_w, const float* __restrict__ gn_b,
    const int* __restrict__ ip)
{
    __shared__ float sh_r[4][64];
    __shared__ float red[4][2], red2[4][2];
    int t = threadIdx.x;
    int hl = t >> 6, j = t & 63;
    int blk = blockIdx.x;
    int b = blk >> 3;
    int h = ((blk & 7) << 2) + hl;
    size_t idx = (size_t)b * EMB + h * HS + j;
    float rv = g_r[idx], kv = g_k[idx], vv = g_v[idx];
    float fav = faaaa[h * HS + j];
    sh_r[hl][j] = rv;
    int wig = (t >> 5) & 1;

    float p = rv * fav * kv;
#pragma unroll
    for (int o = 16; o > 0; o >>= 1) p += __shfl_xor_sync(0xffffffffu, p, o);
    if ((t & 31) == 0) red[hl][wig] = p;
    __syncthreads();
    float c = red[hl][0] + red[hl][1];

    int i = ip[0];
    const float* s0 = state + ((size_t)b * SROWS + (size_t)((2 + HS) * i + 2 + 2 * h)) * EMB + j;
    const float* s1 = s0 + EMB;
    float acc = 0.f;
#pragma unroll
    for (int si = 0; si < 32; si++) acc += sh_r[hl][si] * s0[si * 64];
#pragma unroll
    for (int si = 0; si < 32; si++) acc += sh_r[hl][si + 32] * s1[si * 64];
    float y = c * vv + acc;

    float sy = y, sy2 = y * y;
#pragma unroll
    for (int o = 16; o > 0; o >>= 1) {
        sy  += __shfl_xor_sync(0xffffffffu, sy,  o);
        sy2 += __shfl_xor_sync(0xffffffffu, sy2, o);
    }
    __syncthreads();
    if ((t & 31) == 0) { red[hl][wig] = sy; red2[hl][wig] = sy2; }
    __syncthreads();
    float mu  = (red[hl][0] + red[hl][1]) * (1.0f / HS);
    float var = (red2[hl][0] + red2[hl][1]) * (1.0f / HS) - mu * mu;
    float yg = (y - mu) * rsqrtf(var + 1e-5f);
    int e = h * HS + j;
    h_ygg[idx] = __float2half((yg * gn_w[e] + gn_b[e]) * g_g[idx]);
}

// ================= host =================
static void* sym_addr(const void* symbol)
{
    void* p = nullptr;
    cudaGetSymbolAddress(&p, symbol);
    return p;
}

extern "C" void kernel_launch(void* const* d_in, const int* in_sizes, int n_in,
                              void* d_out, int out_size)
{
    const float* x       = (const float*)d_in[0];
    const float* state   = (const float*)d_in[1];
    const float* ln1_w   = (const float*)d_in[2];
    const float* ln1_b   = (const float*)d_in[3];
    const float* ln2_w   = (const float*)d_in[4];
    const float* ln2_b   = (const float*)d_in[5];
    const float* maa_x   = (const float*)d_in[6];
    const float* maa_k   = (const float*)d_in[8];
    const float* maa_v   = (const float*)d_in[9];
    const float* maa_r   = (const float*)d_in[10];
    const float* maa_g   = (const float*)d_in[11];
    const float* maa_w1  = (const float*)d_in[12];
    const float* maa_w2  = (const float*)d_in[13];
    const float* faaaa   = (const float*)d_in[17];
    const float* Wr      = (const float*)d_in[18];
    const float* Wk      = (const float*)d_in[19];
    const float* Wv      = (const float*)d_in[20];
    const float* Wo      = (const float*)d_in[21];
    const float* Wg      = (const float*)d_in[22];
    const float* gn_w    = (const float*)d_in[23];
    const float* gn_b    = (const float*)d_in[24];
    const float* fmk     = (const float*)d_in[25];
    const float* fmr     = (const float*)d_in[26];
    const float* ffn_Wk  = (const float*)d_in[27];
    const float* ffn_Wr  = (const float*)d_in[28];
    const float* ffn_Wv  = (const float*)d_in[29];
    const int*   ip      = (const int*)d_in[30];
    float* out = (float*)d_out;

    float* p_r   = (float*)sym_addr(g_r);
    float* p_k   = (float*)sym_addr(g_k);
    float* p_v   = (float*)sym_addr(g_v);
    float* p_g   = (float*)sym_addr(g_g);
    float* p_x1  = (float*)sym_addr(g_x1);
    float* p_rr  = (float*)sym_addr(g_rr);
    __half* ph_xr  = (__half*)sym_addr(h_xr);
    __half* ph_xk  = (__half*)sym_addr(h_xk);
    __half* ph_xv  = (__half*)sym_addr(h_xv);
    __half* ph_xg  = (__half*)sym_addr(h_xg);
    __half* ph_ygg = (__half*)sym_addr(h_ygg);
    __half* ph_xk2 = (__half*)sym_addr(h_xk2);
    __half* ph_xr2 = (__half*)sym_addr(h_xr2);
    __half* ph_kk  = (__half*)sym_addr(h_kk);
    __half* ph_w   = (__half*)sym_addr(h_w);

    cudaFuncSetAttribute(gemm_mma, cudaFuncAttributeMaxDynamicSharedMemorySize, GSMEM_BYTES);

    const size_t WSZ = (size_t)EMB * EMB;
    __half* w_r  = ph_w + 0 * WSZ;
    __half* w_k  = ph_w + 1 * WSZ;
    __half* w_v  = ph_w + 2 * WSZ;
    __half* w_g  = ph_w + 3 * WSZ;
    __half* w_o  = ph_w + 4 * WSZ;
    __half* w_fr = ph_w + 5 * WSZ;
    __half* w_fk = ph_w + 6 * WSZ;
    __half* w_fv = ph_w + 7 * WSZ;

    WCvt wc;
    wc.src[0] = Wr;  wc.src[1] = Wk;  wc.src[2] = Wv;  wc.src[3] = Wg;
    wc.src[4] = Wo;  wc.src[5] = ffn_Wr; wc.src[6] = ffn_Wk; wc.src[7] = ffn_Wv;

    GemmB b1;
    b1.A[0] = ph_xr; b1.W[0] = w_r; b1.C[0] = p_r; b1.ep[0] = 0;
    b1.A[1] = ph_xk; b1.W[1] = w_k; b1.C[1] = p_k; b1.ep[1] = 0;
    b1.A[2] = ph_xv; b1.W[2] = w_v; b1.C[2] = p_v; b1.ep[2] = 0;
    b1.A[3] = ph_xg; b1.W[3] = w_g; b1.C[3] = p_g; b1.ep[3] = 1;
    for (int q = 0; q < 4; q++) { b1.addp[q] = nullptr; b1.gatep[q] = nullptr; b1.Ch[q] = nullptr; }

    GemmB b2;
    for (int q = 0; q < 4; q++) {
        b2.A[q] = ph_ygg; b2.W[q] = w_o; b2.C[q] = p_x1; b2.Ch[q] = nullptr;
        b2.ep[q] = 4; b2.addp[q] = x; b2.gatep[q] = nullptr;
    }

    GemmB b3;
    for (int q = 0; q < 4; q++) { b3.addp[q] = nullptr; b3.gatep[q] = nullptr; b3.Ch[q] = nullptr; }
    b3.A[0] = ph_xr2; b3.W[0] = w_fr; b3.C[0] = p_rr; b3.ep[0] = 2;
    b3.A[1] = ph_xk2; b3.W[1] = w_fk; b3.C[1] = nullptr; b3.Ch[1] = ph_kk; b3.ep[1] = 3;
    b3.A[2] = b3.A[0]; b3.W[2] = b3.W[0]; b3.C[2] = p_rr; b3.ep[2] = 2;
    b3.A[3] = b3.A[0]; b3.W[3] = b3.W[0]; b3.C[3] = p_rr; b3.ep[3] = 2;

    GemmB b4;
    for (int q = 0; q < 4; q++) {
        b4.A[q] = ph_kk; b4.W[q] = w_fv; b4.C[q] = out; b4.Ch[q] = nullptr;
        b4.ep[q] = 5; b4.addp[q] = p_x1; b4.gatep[q] = p_rr;
    }

    dim3 blk(256);
    dim3 gG(EMB / TN, NB / TM);

    // launch 1: fused LN1 + weight conversion (keeps gemm b1 at position 4 for ncu)
    ln1_wcvt_kernel<<<NB + 8 * WCVT_BLKS_PER_W, blk>>>(x, state, ln1_w, ln1_b, maa_x, ip, wc);
    gemm_w1_tanh<<<dim3(320 / 64, NB / 32), blk>>>(maa_w1);
    mix_kernel<<<dim3(EMB / 64, NB / 64, 4), blk>>>(maa_w2, maa_k, maa_v, maa_r, maa_g);

    gemm_mma<<<dim3(gG.x, gG.y, 4), 256, GSMEM_BYTES>>>(b1);

    wkv_kernel<<<NB * NH / 4, blk>>>(faaaa, state, gn_w, gn_b, ip);

    gemm_mma<<<dim3(gG.x, gG.y, 1), 256, GSMEM_BYTES>>>(b2);

    ln2_kernel<<<NB, blk>>>(state, ln2_w, ln2_b, fmk, fmr, ip);

    gemm_mma<<<dim3(gG.x, gG.y, 2), 256, GSMEM_BYTES>>>(b3);

    gemm_mma<<<dim3(gG.x, gG.y, 1), 256, GSMEM_BYTES>>>(b4);
}

// round 11
// speedup vs baseline: 1.0665x; 1.0665x over previous
#include <cuda_runtime.h>
#include <cuda_fp16.h>
#include <math.h>
#include <stdint.h>

#define EMB 2048
#define NB 1024
#define NH 32
#define HS 64
#define SROWS 66

// ================= device scratch =================
__device__ float g_xn [NB * EMB];
__device__ float g_sx [NB * EMB];
__device__ float g_xin[NB * EMB];
__device__ float g_x5 [NB * 320];
__device__ float g_r  [NB * EMB];
__device__ float g_k  [NB * EMB];
__device__ float g_v  [NB * EMB];
__device__ float g_g  [NB * EMB];
__device__ float g_x1 [NB * EMB];
__device__ float g_rr [NB * EMB];

__device__ __half h_xr [NB * EMB];
__device__ __half h_xk [NB * EMB];
__device__ __half h_xv [NB * EMB];
__device__ __half h_xg [NB * EMB];
__device__ __half h_ygg[NB * EMB];
__device__ __half h_xk2[NB * EMB];
__device__ __half h_xr2[NB * EMB];
__device__ __half h_kk [NB * EMB];
__device__ __half h_w  [8 * EMB * EMB];

// ================= helpers =================
__device__ __forceinline__ uint32_t smem_u32(const void* p) {
    uint32_t a;
    asm("{ .reg .u64 t; cvta.to.shared.u64 t, %1; cvt.u32.u64 %0, t; }" : "=r"(a) : "l"(p));
    return a;
}

#define CP_ASYNC16(dst, src) \
    asm volatile("cp.async.cg.shared.global [%0], [%1], 16;" :: "r"(dst), "l"(src))
#define CP_COMMIT() asm volatile("cp.async.commit_group;" ::: "memory")
#define CP_WAIT0()  asm volatile("cp.async.wait_group 0;" ::: "memory")
#define CP_WAIT1()  asm volatile("cp.async.wait_group 1;" ::: "memory")
#define CP_WAIT2()  asm volatile("cp.async.wait_group 2;" ::: "memory")

__device__ __forceinline__ void mma_f16(float& c0, float& c1, float& c2, float& c3,
                                        uint32_t a0, uint32_t a1, uint32_t a2, uint32_t a3,
                                        uint32_t b0, uint32_t b1) {
    asm volatile(
        "mma.sync.aligned.m16n8k16.row.col.f32.f16.f16.f32 "
        "{%0,%1,%2,%3}, {%4,%5,%6,%7}, {%8,%9}, {%0,%1,%2,%3};"
        : "+f"(c0), "+f"(c1), "+f"(c2), "+f"(c3)
        : "r"(a0), "r"(a1), "r"(a2), "r"(a3), "r"(b0), "r"(b1));
}

// ================= fused LayerNorm1 + weight fp32->fp16 conversion =================
struct WCvt { const float* src[8]; };
#define WCVT_BLKS_PER_W 4096

__global__ __launch_bounds__(256) void ln1_wcvt_kernel(
    const float* __restrict__ x, const float* __restrict__ state,
    const float* __restrict__ w, const float* __restrict__ bvec,
    const float* __restrict__ maa_x, const int* __restrict__ ip,
    const WCvt wc)
{
    int bid = blockIdx.x;
    int t = threadIdx.x;
    if (bid >= NB) {
        int r = bid - NB;
        int z = r >> 12;
        int blk = r & 4095;
        const float* s = wc.src[z];
        __half* d = h_w + (size_t)z * EMB * EMB;
        int i = (blk * 256 + t) * 4;
        float4 f = *(const float4*)(s + i);
        __half2 lo = __floats2half2_rn(f.x, f.y);
        __half2 hi = __floats2half2_rn(f.z, f.w);
        *(uint2*)(d + i) = make_uint2(*(uint32_t*)&lo, *(uint32_t*)&hi);
        return;
    }
    __shared__ float sh[8], sh2[8];
    int b = bid;
    const float* xr = x + (size_t)b * EMB;
    float v[8];
    float s = 0.f, s2 = 0.f;
#pragma unroll
    for (int u = 0; u < 2; u++) {
        float4 f = *(const float4*)(xr + t * 8 + u * 4);
        v[u*4+0] = f.x; v[u*4+1] = f.y; v[u*4+2] = f.z; v[u*4+3] = f.w;
    }
#pragma unroll
    for (int q = 0; q < 8; q++) { s += v[q]; s2 += v[q] * v[q]; }
#pragma unroll
    for (int o = 16; o > 0; o >>= 1) {
        s  += __shfl_xor_sync(0xffffffffu, s,  o);
        s2 += __shfl_xor_sync(0xffffffffu, s2, o);
    }
    if ((t & 31) == 0) { sh[t >> 5] = s; sh2[t >> 5] = s2; }
    __syncthreads();
    s = 0.f; s2 = 0.f;
#pragma unroll
    for (int q = 0; q < 8; q++) { s += sh[q]; s2 += sh2[q]; }
    float mu  = s * (1.0f / EMB);
    float var = s2 * (1.0f / EMB) - mu * mu;
    float rinv = rsqrtf(var + 1e-5f);
    int i = ip[0];
    const float* srow = state + ((size_t)b * SROWS + (size_t)((2 + HS) * i + 1)) * EMB;
#pragma unroll
    for (int q = 0; q < 8; q++) {
        int e = t * 8 + q;
        float xnv = (v[q] - mu) * rinv * w[e] + bvec[e];
        float sxv = srow[e] - xnv;
        size_t o = (size_t)b * EMB + e;
        g_xn[o] = xnv;
        g_sx[o] = sxv;
        g_xin[o] = xnv + sxv * maa_x[e];
    }
}

// ================= fp16 mma GEMM NT =================
// 256 threads, 8 warps 2(M)x4(N); warp tile 32x32; CTA tile 64x128; TK=32; 3 stages.
#define TM 64
#define TN 128
#define TK 32
#define PADH 40                        // halfs per row (32 + 8 pad)
#define ATILE_H (TM * PADH)            // 2560 halfs
#define BTILE_H (TN * PADH)            // 5120 halfs
#define STG_H (ATILE_H + BTILE_H)      // 7680 halfs
#define STG_BYTES (STG_H * 2)          // 15360 B
#define NC (EMB / TK)                  // 64
#define GSMEM_BYTES (3 * STG_BYTES)    // 46080

// EP: 0 none, 1 silu, 2 sigmoid, 3 relu^2 -> half, 4 add, 5 add + gate*acc
struct GemmB {
    const __half* A[4];
    const __half* W[4];
    float* C[4];
    __half* Ch[4];
    const float* addp[4];
    const float* gatep[4];
    int ep[4];
};

__global__ void __launch_bounds__(256, 3) gemm_mma(const GemmB q)
{
    extern __shared__ __align__(16) __half smem[];
    int z = blockIdx.z;
    const __half* Ag = q.A[z];
    const __half* Wg = q.W[z];
    float* C = q.C[z];
    __half* Ch = q.Ch[z];
    const float* add  = q.addp[z];
    const float* gate = q.gatep[z];
    int ep = q.ep[z];

    int tid  = threadIdx.x;
    int lane = tid & 31;
    int wid  = tid >> 5;
    int wm = wid >> 2, wn = wid & 3;   // 2 x 4 warp grid, tiles 32x32
    int gq = lane >> 2, tq = lane & 3;

    int m0 = blockIdx.y * TM;
    int n0 = blockIdx.x * TN;

    const __half* Abase = Ag + (size_t)m0 * EMB;
    const __half* Wbase = Wg + (size_t)n0 * EMB;

    uint32_t smem_b = smem_u32(smem);

    int srow = tid >> 2;               // 0..63
    int scol = (tid & 3) * 8;          // halfs: 0,8,16,24

    float acc[2][4][4];
#pragma unroll
    for (int i = 0; i < 2; i++)
#pragma unroll
        for (int j = 0; j < 4; j++)
#pragma unroll
            for (int u = 0; u < 4; u++) acc[i][j][u] = 0.f;

    // prologue: chunks 0 and 1
#pragma unroll
    for (int ci = 0; ci < 2; ci++) {
        uint32_t sA = smem_b + ci * STG_BYTES;
        uint32_t sB = sA + ATILE_H * 2;
        int k0 = ci * TK;
        CP_ASYNC16(sA + (srow * PADH + scol) * 2, Abase + (size_t)srow * EMB + k0 + scol);
        CP_ASYNC16(sB + (srow * PADH + scol) * 2, Wbase + (size_t)srow * EMB + k0 + scol);
        CP_ASYNC16(sB + ((srow + 64) * PADH + scol) * 2, Wbase + (size_t)(srow + 64) * EMB + k0 + scol);
        CP_COMMIT();
    }

    for (int c = 0; c < NC; c++) {
        int s = c % 3;
        if (c + 2 < NC) {
            int sn = (c + 2) % 3;
            uint32_t sA = smem_b + sn * STG_BYTES;
            uint32_t sB = sA + ATILE_H * 2;
            int k0 = (c + 2) * TK;
            CP_ASYNC16(sA + (srow * PADH + scol) * 2, Abase + (size_t)srow * EMB + k0 + scol);
            CP_ASYNC16(sB + (srow * PADH + scol) * 2, Wbase + (size_t)srow * EMB + k0 + scol);
            CP_ASYNC16(sB + ((srow + 64) * PADH + scol) * 2, Wbase + (size_t)(srow + 64) * EMB + k0 + scol);
            CP_COMMIT();
            CP_WAIT2();
        } else if (c + 1 < NC) {
            CP_WAIT1();
        } else {
            CP_WAIT0();
        }
        __syncthreads();

        const uint32_t* As32 = reinterpret_cast<const uint32_t*>(smem + s * STG_H);
        const uint32_t* Bs32 = As32 + ATILE_H / 2;

#pragma unroll
        for (int ks = 0; ks < 2; ks++) {
            int kb2 = ks * 8;
            uint32_t a[2][4];
#pragma unroll
            for (int ma = 0; ma < 2; ma++) {
                int row = wm * 32 + ma * 16 + gq;
                int base = row * (PADH / 2) + kb2 + tq;
                a[ma][0] = As32[base];
                a[ma][1] = As32[base + 8 * (PADH / 2)];
                a[ma][2] = As32[base + 4];
                a[ma][3] = As32[base + 8 * (PADH / 2) + 4];
            }
            uint32_t b[4][2];
#pragma unroll
            for (int na = 0; na < 4; na++) {
                int col = wn * 32 + na * 8 + gq;
                int base = col * (PADH / 2) + kb2 + tq;
                b[na][0] = Bs32[base];
                b[na][1] = Bs32[base + 4];
            }
#pragma unroll
            for (int ma = 0; ma < 2; ma++)
#pragma unroll
                for (int na = 0; na < 4; na++)
                    mma_f16(acc[ma][na][0], acc[ma][na][1], acc[ma][na][2], acc[ma][na][3],
                            a[ma][0], a[ma][1], a[ma][2], a[ma][3],
                            b[na][0], b[na][1]);
        }
        __syncthreads();
    }

#pragma unroll
    for (int ma = 0; ma < 2; ma++) {
#pragma unroll
        for (int na = 0; na < 4; na++) {
            int r0 = m0 + wm * 32 + ma * 16 + gq;
            int c0 = n0 + wn * 32 + na * 8 + 2 * tq;
#pragma unroll
            for (int half_ = 0; half_ < 2; half_++) {
                int rr = r0 + half_ * 8;
                size_t o = (size_t)rr * EMB + c0;
                float v0 = acc[ma][na][half_ * 2 + 0];
                float v1 = acc[ma][na][half_ * 2 + 1];
                if (ep == 1)      { v0 = v0 / (1.f + expf(-v0)); v1 = v1 / (1.f + expf(-v1)); }
                else if (ep == 2) { v0 = 1.f / (1.f + expf(-v0)); v1 = 1.f / (1.f + expf(-v1)); }
                else if (ep == 3) {
                    v0 = fmaxf(v0, 0.f); v1 = fmaxf(v1, 0.f);
                    __half2 hv = __floats2half2_rn(v0 * v0, v1 * v1);
                    *(uint32_t*)(Ch + o) = *(uint32_t*)&hv;
                    continue;
                }
                else if (ep == 4) { v0 = add[o] + v0; v1 = add[o + 1] + v1; }
                else if (ep == 5) { v0 = add[o] + gate[o] * v0; v1 = add[o + 1] + gate[o + 1] * v1; }
                *(float2*)(C + o) = make_float2(v0, v1);
            }
        }
    }
}

// ================= LayerNorm 2 (outputs half) =================
__global__ __launch_bounds__(256) void ln2_kernel(
    const float* __restrict__ state,
    const float* __restrict__ w, const float* __restrict__ bvec,
    const float* __restrict__ fmk, const float* __restrict__ fmr,
    const int* __restrict__ ip)
{
    __shared__ float sh[8], sh2[8];
    int b = blockIdx.x, t = threadIdx.x;
    const float* xr = g_x1 + (size_t)b * EMB;
    float v[8];
    float s = 0.f, s2 = 0.f;
#pragma unroll
    for (int u = 0; u < 2; u++) {
        float4 f = *(const float4*)(xr + t * 8 + u * 4);
        v[u*4+0] = f.x; v[u*4+1] = f.y; v[u*4+2] = f.z; v[u*4+3] = f.w;
    }
#pragma unroll
    for (int q = 0; q < 8; q++) { s += v[q]; s2 += v[q] * v[q]; }
#pragma unroll
    for (int o = 16; o > 0; o >>= 1) {
        s  += __shfl_xor_sync(0xffffffffu, s,  o);
        s2 += __shfl_xor_sync(0xffffffffu, s2, o);
    }
    if ((t & 31) == 0) { sh[t >> 5] = s; sh2[t >> 5] = s2; }
    __syncthreads();
    s = 0.f; s2 = 0.f;
#pragma unroll
    for (int q = 0; q < 8; q++) { s += sh[q]; s2 += sh2[q]; }
    float mu  = s * (1.0f / EMB);
    float var = s2 * (1.0f / EMB) - mu * mu;
    float rinv = rsqrtf(var + 1e-5f);
    int i = ip[0];
    const float* srow = state + ((size_t)b * SROWS + (size_t)((2 + HS) * i)) * EMB;
#pragma unroll
    for (int q = 0; q < 8; q++) {
        int e = t * 8 + q;
        float xnv = (v[q] - mu) * rinv * w[e] + bvec[e];
        float sxv = srow[e] - xnv;
        size_t o = (size_t)b * EMB + e;
        h_xk2[o] = __float2half(xnv + sxv * fmk[e]);
        h_xr2[o] = __float2half(xnv + sxv * fmr[e]);
    }
}

// ================= small GEMM: x5 = tanh(xin @ maa_w1), tile 32x64 ====
__global__ __launch_bounds__(256) void gemm_w1_tanh(const float* __restrict__ W1)
{
    __shared__ float As[16][36];
    __shared__ float Ws[16][68];
    int t = threadIdx.x;
    int bm0 = blockIdx.y * 32, bn0 = blockIdx.x * 64;
    int tm = (t >> 4) * 2, tn = (t & 15) * 4;
    float acc[2][4] = {};
    for (int k0 = 0; k0 < EMB; k0 += 16) {
        float2 a = *(const float2*)(g_xin + (size_t)(bm0 + (t >> 3)) * EMB + k0 + (t & 7) * 2);
        float4 w = *(const float4*)(W1 + (size_t)(k0 + (t >> 4)) * 320 + bn0 + (t & 15) * 4);
        __syncthreads();
        As[(t & 7) * 2 + 0][t >> 3] = a.x;
        As[(t & 7) * 2 + 1][t >> 3] = a.y;
        *(float4*)&Ws[t >> 4][(t & 15) * 4] = w;
        __syncthreads();
#pragma unroll
        for (int kk = 0; kk < 16; kk++) {
            float ra[2], rw[4];
#pragma unroll
            for (int q = 0; q < 2; q++) ra[q] = As[kk][tm + q];
#pragma unroll
            for (int q = 0; q < 4; q++) rw[q] = Ws[kk][tn + q];
#pragma unroll
            for (int iq = 0; iq < 2; iq++)
#pragma unroll
                for (int jq = 0; jq < 4; jq++)
                    acc[iq][jq] += ra[iq] * rw[jq];
        }
    }
#pragma unroll
    for (int iq = 0; iq < 2; iq++)
#pragma unroll
        for (int jq = 0; jq < 4; jq++) {
            int m = bm0 + tm + iq, n = bn0 + tn + jq;
            g_x5[(size_t)m * 320 + n] = tanhf(acc[iq][jq]);
        }
}

// ================= mix (outputs half) =================
__global__ __launch_bounds__(256) void mix_kernel(
    const float* __restrict__ maa_w2,
    const float* __restrict__ mk, const float* __restrict__ mv,
    const float* __restrict__ mr, const float* __restrict__ mg)
{
    __shared__ float As[16][68];
    __shared__ float Ws[16][68];
    int z = blockIdx.z, jj = z + 1;
    const float* A = g_x5 + jj * 64;
    const float* W = maa_w2 + (size_t)jj * 64 * EMB;
    const float* vec = (z == 0) ? mk : (z == 1) ? mv : (z == 2) ? mr : mg;
    __half* out = (z == 0) ? h_xk : (z == 1) ? h_xv : (z == 2) ? h_xr : h_xg;
    int t = threadIdx.x;
    int bm0 = blockIdx.y * 64, bn0 = blockIdx.x * 64;
    int tm = (t >> 4) * 4, tn = (t & 15) * 4;
    float acc[4][4] = {};
    for (int k0 = 0; k0 < 64; k0 += 16) {
        float4 a = *(const float4*)(A + (size_t)(bm0 + (t >> 2)) * 320 + k0 + (t & 3) * 4);
        float4 w = *(const float4*)(W + (size_t)(k0 + (t >> 4)) * EMB + bn0 + (t & 15) * 4);
        __syncthreads();
        As[(t&3)*4+0][t>>2] = a.x; As[(t&3)*4+1][t>>2] = a.y;
        As[(t&3)*4+2][t>>2] = a.z; As[(t&3)*4+3][t>>2] = a.w;
        *(float4*)&Ws[t >> 4][(t & 15) * 4] = w;
        __syncthreads();
#pragma unroll
        for (int kk = 0; kk < 16; kk++) {
            float ra[4], rw[4];
#pragma unroll
            for (int q = 0; q < 4; q++) ra[q] = As[kk][tm + q];
#pragma unroll
            for (int q = 0; q < 4; q++) rw[q] = Ws[kk][tn + q];
#pragma unroll
            for (int iq = 0; iq < 4; iq++)
#pragma unroll
                for (int jq = 0; jq < 4; jq++)
                    acc[iq][jq] += ra[iq] * rw[jq];
        }
    }
#pragma unroll
    for (int iq = 0; iq < 4; iq++)
#pragma unroll
        for (int jq = 0; jq < 4; jq++) {
            int m = bm0 + tm + iq, n = bn0 + tn + jq;
            size_t o = (size_t)m * EMB + n;
            out[o] = __float2half(g_xn[o] + g_sx[o] * (vec[n] + acc[iq][jq]));
        }
}

// ================= WKV + GroupNorm + gate (output half) =================
__global__ __launch_bounds__(256) void wkv_kernel(
    const float* __restrict__ faaaa, const float* __restrict__ state,
    const float* __restrict__ gn_w, const float* __restrict__ gn_b,
    const int* __restrict__ ip)
{
    __shared__ float sh_r[4][64];
    __shared__ float red[4][2], red2[4][2];
    int t = threadIdx.x;
    int hl = t >> 6, j = t & 63;
    int blk = blockIdx.x;
    int b = blk >> 3;
    int h = ((blk & 7) << 2) + hl;
    size_t idx = (size_t)b * EMB + h * HS + j;
    float rv = g_r[idx], kv = g_k[idx], vv = g_v[idx];
    float fav = faaaa[h * HS + j];
    sh_r[hl][j] = rv;
    int wig = (t >> 5) & 1;

    float p = rv * fav * kv;
#pragma unroll
    for (int o = 16; o > 0; o >>= 1) p += __shfl_xor_sync(0xffffffffu, p, o);
    if ((t & 31) == 0) red[hl][wig] = p;
    __syncthreads();
    float c = red[hl][0] + red[hl][1];

    int i = ip[0];
    const float* s0 = state + ((size_t)b * SROWS + (size_t)((2 + HS) * i + 2 + 2 * h)) * EMB + j;
    const float* s1 = s0 + EMB;
    float acc = 0.f;
#pragma unroll
    for (int si = 0; si < 32; si++) acc += sh_r[hl][si] * s0[si * 64];
#pragma unroll
    for (int si = 0; si < 32; si++) acc += sh_r[hl][si + 32] * s1[si * 64];
    float y = c * vv + acc;

    float sy = y, sy2 = y * y;
#pragma unroll
    for (int o = 16; o > 0; o >>= 1) {
        sy  += __shfl_xor_sync(0xffffffffu, sy,  o);
        sy2 += __shfl_xor_sync(0xffffffffu, sy2, o);
    }
    __syncthreads();
    if ((t & 31) == 0) { red[hl][wig] = sy; red2[hl][wig] = sy2; }
    __syncthreads();
    float mu  = (red[hl][0] + red[hl][1]) * (1.0f / HS);
    float var = (red2[hl][0] + red2[hl][1]) * (1.0f / HS) - mu * mu;
    float yg = (y - mu) * rsqrtf(var + 1e-5f);
    int e = h * HS + j;
    h_ygg[idx] = __float2half((yg * gn_w[e] + gn_b[e]) * g_g[idx]);
}

// ================= host =================
static void* sym_addr(const void* symbol)
{
    void* p = nullptr;
    cudaGetSymbolAddress(&p, symbol);
    return p;
}

extern "C" void kernel_launch(void* const* d_in, const int* in_sizes, int n_in,
                              void* d_out, int out_size)
{
    const float* x       = (const float*)d_in[0];
    const float* state   = (const float*)d_in[1];
    const float* ln1_w   = (const float*)d_in[2];
    const float* ln1_b   = (const float*)d_in[3];
    const float* ln2_w   = (const float*)d_in[4];
    const float* ln2_b   = (const float*)d_in[5];
    const float* maa_x   = (const float*)d_in[6];
    const float* maa_k   = (const float*)d_in[8];
    const float* maa_v   = (const float*)d_in[9];
    const float* maa_r   = (const float*)d_in[10];
    const float* maa_g   = (const float*)d_in[11];
    const float* maa_w1  = (const float*)d_in[12];
    const float* maa_w2  = (const float*)d_in[13];
    const float* faaaa   = (const float*)d_in[17];
    const float* Wr      = (const float*)d_in[18];
    const float* Wk      = (const float*)d_in[19];
    const float* Wv      = (const float*)d_in[20];
    const float* Wo      = (const float*)d_in[21];
    const float* Wg      = (const float*)d_in[22];
    const float* gn_w    = (const float*)d_in[23];
    const float* gn_b    = (const float*)d_in[24];
    const float* fmk     = (const float*)d_in[25];
    const float* fmr     = (const float*)d_in[26];
    const float* ffn_Wk  = (const float*)d_in[27];
    const float* ffn_Wr  = (const float*)d_in[28];
    const float* ffn_Wv  = (const float*)d_in[29];
    const int*   ip      = (const int*)d_in[30];
    float* out = (float*)d_out;

    float* p_r   = (float*)sym_addr(g_r);
    float* p_k   = (float*)sym_addr(g_k);
    float* p_v   = (float*)sym_addr(g_v);
    float* p_g   = (float*)sym_addr(g_g);
    float* p_x1  = (float*)sym_addr(g_x1);
    float* p_rr  = (float*)sym_addr(g_rr);
    __half* ph_xr  = (__half*)sym_addr(h_xr);
    __half* ph_xk  = (__half*)sym_addr(h_xk);
    __half* ph_xv  = (__half*)sym_addr(h_xv);
    __half* ph_xg  = (__half*)sym_addr(h_xg);
    __half* ph_ygg = (__half*)sym_addr(h_ygg);
    __half* ph_xk2 = (__half*)sym_addr(h_xk2);
    __half* ph_xr2 = (__half*)sym_addr(h_xr2);
    __half* ph_kk  = (__half*)sym_addr(h_kk);
    __half* ph_w   = (__half*)sym_addr(h_w);

    cudaFuncSetAttribute(gemm_mma, cudaFuncAttributeMaxDynamicSharedMemorySize, GSMEM_BYTES);

    const size_t WSZ = (size_t)EMB * EMB;
    __half* w_r  = ph_w + 0 * WSZ;
    __half* w_k  = ph_w + 1 * WSZ;
    __half* w_v  = ph_w + 2 * WSZ;
    __half* w_g  = ph_w + 3 * WSZ;
    __half* w_o  = ph_w + 4 * WSZ;
    __half* w_fr = ph_w + 5 * WSZ;
    __half* w_fk = ph_w + 6 * WSZ;
    __half* w_fv = ph_w + 7 * WSZ;

    WCvt wc;
    wc.src[0] = Wr;  wc.src[1] = Wk;  wc.src[2] = Wv;  wc.src[3] = Wg;
    wc.src[4] = Wo;  wc.src[5] = ffn_Wr; wc.src[6] = ffn_Wk; wc.src[7] = ffn_Wv;

    GemmB b1;
    b1.A[0] = ph_xr; b1.W[0] = w_r; b1.C[0] = p_r; b1.ep[0] = 0;
    b1.A[1] = ph_xk; b1.W[1] = w_k; b1.C[1] = p_k; b1.ep[1] = 0;
    b1.A[2] = ph_xv; b1.W[2] = w_v; b1.C[2] = p_v; b1.ep[2] = 0;
    b1.A[3] = ph_xg; b1.W[3] = w_g; b1.C[3] = p_g; b1.ep[3] = 1;
    for (int q = 0; q < 4; q++) { b1.addp[q] = nullptr; b1.gatep[q] = nullptr; b1.Ch[q] = nullptr; }

    GemmB b2;
    for (int q = 0; q < 4; q++) {
        b2.A[q] = ph_ygg; b2.W[q] = w_o; b2.C[q] = p_x1; b2.Ch[q] = nullptr;
        b2.ep[q] = 4; b2.addp[q] = x; b2.gatep[q] = nullptr;
    }

    GemmB b3;
    for (int q = 0; q < 4; q++) { b3.addp[q] = nullptr; b3.gatep[q] = nullptr; b3.Ch[q] = nullptr; }
    b3.A[0] = ph_xr2; b3.W[0] = w_fr; b3.C[0] = p_rr; b3.ep[0] = 2;
    b3.A[1] = ph_xk2; b3.W[1] = w_fk; b3.C[1] = nullptr; b3.Ch[1] = ph_kk; b3.ep[1] = 3;
    b3.A[2] = b3.A[0]; b3.W[2] = b3.W[0]; b3.C[2] = p_rr; b3.ep[2] = 2;
    b3.A[3] = b3.A[0]; b3.W[3] = b3.W[0]; b3.C[3] = p_rr; b3.ep[3] = 2;

    GemmB b4;
    for (int q = 0; q < 4; q++) {
        b4.A[q] = ph_kk; b4.W[q] = w_fv; b4.C[q] = out; b4.Ch[q] = nullptr;
        b4.ep[q] = 5; b4.addp[q] = p_x1; b4.gatep[q] = p_rr;
    }

    dim3 blk(256);
    dim3 gG(EMB / TN, NB / TM);   // (16, 16)

    ln1_wcvt_kernel<<<NB + 8 * WCVT_BLKS_PER_W, blk>>>(x, state, ln1_w, ln1_b, maa_x, ip, wc);
    gemm_w1_tanh<<<dim3(320 / 64, NB / 32), blk>>>(maa_w1);
    mix_kernel<<<dim3(EMB / 64, NB / 64, 4), blk>>>(maa_w2, maa_k, maa_v, maa_r, maa_g);

    gemm_mma<<<dim3(gG.x, gG.y, 4), 256, GSMEM_BYTES>>>(b1);

    wkv_kernel<<<NB * NH / 4, blk>>>(faaaa, state, gn_w, gn_b, ip);

    gemm_mma<<<dim3(gG.x, gG.y, 1), 256, GSMEM_BYTES>>>(b2);

    ln2_kernel<<<NB, blk>>>(state, ln2_w, ln2_b, fmk, fmr, ip);

    gemm_mma<<<dim3(gG.x, gG.y, 2), 256, GSMEM_BYTES>>>(b3);

    gemm_mma<<<dim3(gG.x, gG.y, 1), 256, GSMEM_BYTES>>>(b4);
}